// round 1
// baseline (speedup 1.0000x reference)
#include <cuda_runtime.h>
#include <math.h>

// Problem constants
#define B_  8
#define T_  1024
#define D_  1024
#define H_  16
#define DH_ 64
#define M_  (B_*T_)     // 8192 rows
#define N3_ (3*D_)      // 3072
#define HALF_D (D_/2)   // 512

// ---------------- scratch (static device globals; no allocations) -------------
__device__ float g_xn[M_*D_];            // layernorm output           (33.5 MB)
__device__ float g_qkv[M_*N3_];          // qkv after rope, row-major  (100 MB)
__device__ float g_attn[M_*D_];          // attention output           (33.5 MB)
__device__ float g_sin[T_*HALF_D];       // rope tables (4 MB)
__device__ float g_cos[T_*HALF_D];
__device__ int   g_len[B_];

// ---------------- layernorm: one block per row --------------------------------
__global__ void __launch_bounds__(256) ln_kernel(const float* __restrict__ x,
                                                 const float* __restrict__ gamma,
                                                 const float* __restrict__ beta) {
    __shared__ float ssum[8], ssq[8];
    const int row = blockIdx.x;
    const int tid = threadIdx.x;
    float4 v = *(const float4*)(x + (size_t)row * D_ + tid * 4);
    float s = v.x + v.y + v.z + v.w;
    float q = v.x*v.x + v.y*v.y + v.z*v.z + v.w*v.w;
    #pragma unroll
    for (int o = 16; o > 0; o >>= 1) {
        s += __shfl_down_sync(0xffffffffu, s, o);
        q += __shfl_down_sync(0xffffffffu, q, o);
    }
    if ((tid & 31) == 0) { ssum[tid >> 5] = s; ssq[tid >> 5] = q; }
    __syncthreads();
    float ts = 0.f, tq = 0.f;
    #pragma unroll
    for (int i = 0; i < 8; i++) { ts += ssum[i]; tq += ssq[i]; }
    const float mu  = ts * (1.f / 1024.f);
    const float var = tq * (1.f / 1024.f) - mu * mu;
    const float inv = rsqrtf(var + 1e-5f);
    float4 g  = *(const float4*)(gamma + tid * 4);
    float4 be = *(const float4*)(beta  + tid * 4);
    float4 out;
    out.x = (v.x - mu) * inv * g.x + be.x;
    out.y = (v.y - mu) * inv * g.y + be.y;
    out.z = (v.z - mu) * inv * g.z + be.z;
    out.w = (v.w - mu) * inv * g.w + be.w;
    *(float4*)(g_xn + (size_t)row * D_ + tid * 4) = out;
}

// ---------------- rope tables (fp32 only; fp64 is ruinously slow on B300) -----
__global__ void rope_table_kernel() {
    const int idx = blockIdx.x * blockDim.x + threadIdx.x;
    if (idx >= T_ * HALF_D) return;
    const int t = idx >> 9;          // / 512
    const int i = idx & (HALF_D - 1);
    // inv_freq = 100000 ^ (-2/D * (i-1));  e = (i-1)/512 is dyadic-exact in fp32
    const float e   = -(((float)i - 1.0f) * (1.0f / 512.0f));
    const float inv = expf(e * 11.512925464970229f);   // ln(1e5)
    const float ang = (float)t * inv;
    float sn, cs;
    sincosf(ang, &sn, &cs);
    g_sin[idx] = sn;
    g_cos[idx] = cs;
}

// ---------------- sequence lengths (mask read as 32-bit words, nonzero=true) --
__global__ void len_kernel(const unsigned int* __restrict__ mask) {
    __shared__ int sc[8];
    const int b = blockIdx.x, tid = threadIdx.x;
    int c = 0;
    for (int i = tid; i < T_; i += 256) c += (mask[b * T_ + i] != 0u);
    #pragma unroll
    for (int o = 16; o > 0; o >>= 1) c += __shfl_down_sync(0xffffffffu, c, o);
    if ((tid & 31) == 0) sc[tid >> 5] = c;
    __syncthreads();
    if (tid == 0) {
        int t = 0;
        #pragma unroll
        for (int i = 0; i < 8; i++) t += sc[i];
        g_len[b] = t;
    }
}

// ---------------- SGEMM 128x128x8, 8x8 per thread, optional rope epilogue -----
template<int N, bool ROPE>
__device__ __forceinline__ void gemm_body(const float* __restrict__ A,
                                          const float* __restrict__ Bm,
                                          const float* __restrict__ bias,
                                          float* __restrict__ C) {
    __shared__ float As[8][128];
    __shared__ float Bs[8][128];
    const int tid = threadIdx.x;
    const int bm = blockIdx.y, bn = blockIdx.x;
    const int arow = tid >> 1, acol = (tid & 1) << 2;
    const int brow = tid >> 5, bcol = (tid & 31) << 2;
    const int tx = tid & 15, ty = tid >> 4;

    const float* Ap = A + (size_t)(bm * 128 + arow) * 1024 + acol;
    const float* Bp = Bm + (size_t)brow * N + bn * 128 + bcol;

    float acc[8][8];
    #pragma unroll
    for (int i = 0; i < 8; i++)
        #pragma unroll
        for (int j = 0; j < 8; j++) acc[i][j] = 0.f;

    for (int k0 = 0; k0 < 1024; k0 += 8) {
        float4 a4 = *(const float4*)(Ap + k0);
        float4 b4 = *(const float4*)(Bp + (size_t)k0 * N);
        As[acol + 0][arow] = a4.x;
        As[acol + 1][arow] = a4.y;
        As[acol + 2][arow] = a4.z;
        As[acol + 3][arow] = a4.w;
        *(float4*)(&Bs[brow][bcol]) = b4;
        __syncthreads();
        #pragma unroll
        for (int kk = 0; kk < 8; kk++) {
            float4 a0 = *(const float4*)(&As[kk][ty * 8]);
            float4 a1 = *(const float4*)(&As[kk][ty * 8 + 4]);
            float4 b0 = *(const float4*)(&Bs[kk][tx * 8]);
            float4 b1 = *(const float4*)(&Bs[kk][tx * 8 + 4]);
            float ar[8] = {a0.x, a0.y, a0.z, a0.w, a1.x, a1.y, a1.z, a1.w};
            float br[8] = {b0.x, b0.y, b0.z, b0.w, b1.x, b1.y, b1.z, b1.w};
            #pragma unroll
            for (int i = 0; i < 8; i++)
                #pragma unroll
                for (int j = 0; j < 8; j++)
                    acc[i][j] = fmaf(ar[i], br[j], acc[i][j]);
        }
        __syncthreads();
    }

    const int row0 = bm * 128 + ty * 8;
    const int col0 = bn * 128 + tx * 8;
    #pragma unroll
    for (int i = 0; i < 8; i++) {
        const int r = row0 + i;
        if (ROPE) {
            const int t = r & (T_ - 1);
            #pragma unroll
            for (int j = 0; j < 8; j += 2) {
                const int c  = col0 + j;
                const int pi = (c & (D_ - 1)) >> 1;     // pair index within D
                const float sn = g_sin[t * HALF_D + pi];
                const float cs = g_cos[t * HALF_D + pi];
                const float e = acc[i][j]     + bias[c];
                const float o = acc[i][j + 1] + bias[c + 1];
                acc[i][j]     = fmaf(e, cs, -o * sn);
                acc[i][j + 1] = fmaf(o, cs,  e * sn);
            }
        } else {
            #pragma unroll
            for (int j = 0; j < 8; j++) acc[i][j] += bias[col0 + j];
        }
        float4* out = (float4*)(C + (size_t)r * N + col0);
        out[0] = make_float4(acc[i][0], acc[i][1], acc[i][2], acc[i][3]);
        out[1] = make_float4(acc[i][4], acc[i][5], acc[i][6], acc[i][7]);
    }
}

__global__ void __launch_bounds__(256) gemm_qkv_kernel(const float* __restrict__ Wqkv,
                                                       const float* __restrict__ bqkv) {
    gemm_body<N3_, true>(g_xn, Wqkv, bqkv, g_qkv);
}

__global__ void __launch_bounds__(256) gemm_out_kernel(const float* __restrict__ Wout,
                                                       const float* __restrict__ bout,
                                                       float* __restrict__ out) {
    gemm_body<D_, false>(g_attn, Wout, bout, out);
}

// ---------------- flash attention: 1 q-row per thread, 32-key tiles -----------
__global__ void __launch_bounds__(256, 1) attn_kernel() {
    __shared__ float ks[32][64];
    __shared__ float vs[32][64];
    __shared__ float scr[32][256];      // score parking (bank-conflict-free)

    const int bh = blockIdx.y;
    const int b = bh >> 4, h = bh & 15;
    const int tid = threadIdx.x;
    const int t = blockIdx.x * 256 + tid;
    const int len = g_len[b];

    const float* qrow = g_qkv + (size_t)(b * T_ + t) * N3_ + h * DH_;
    float q[64];
    #pragma unroll
    for (int i = 0; i < 16; i++) {
        float4 v4 = *(const float4*)(qrow + i * 4);
        q[i*4+0] = v4.x; q[i*4+1] = v4.y; q[i*4+2] = v4.z; q[i*4+3] = v4.w;
    }
    float o[64];
    #pragma unroll
    for (int d = 0; d < 64; d++) o[d] = 0.f;
    float m = -1e30f, l = 0.f;

    const float* kbase = g_qkv + (size_t)(b * T_) * N3_ + D_     + h * DH_;
    const float* vbase = g_qkv + (size_t)(b * T_) * N3_ + 2 * D_ + h * DH_;

    for (int s0 = 0; s0 < T_; s0 += 32) {
        if (s0 >= len) break;   // uniform per block (len shared across block)
        // cooperative K/V tile load: 32 rows x 64 cols each
        #pragma unroll
        for (int p = 0; p < 2; p++) {
            const int idx = tid * 2 + p;
            const int r = idx >> 4, c = (idx & 15) << 2;
            *(float4*)&ks[r][c] = *(const float4*)(kbase + (size_t)(s0 + r) * N3_ + c);
            *(float4*)&vs[r][c] = *(const float4*)(vbase + (size_t)(s0 + r) * N3_ + c);
        }
        __syncthreads();

        const int nv = min(32, len - s0);
        float tmax = -1e30f;
        for (int s = 0; s < 32; s++) {
            float acc = 0.f;
            #pragma unroll
            for (int d4 = 0; d4 < 16; d4++) {
                float4 kv = *(const float4*)&ks[s][d4 * 4];   // LDS.128 broadcast
                acc = fmaf(q[d4*4+0], kv.x, acc);
                acc = fmaf(q[d4*4+1], kv.y, acc);
                acc = fmaf(q[d4*4+2], kv.z, acc);
                acc = fmaf(q[d4*4+3], kv.w, acc);
            }
            acc *= 0.125f;                 // 1/sqrt(64)
            scr[s][tid] = acc;
            if (s < nv) tmax = fmaxf(tmax, acc);
        }
        const float mnew = fmaxf(m, tmax);
        const float corr = expf(m - mnew);
        l *= corr;
        #pragma unroll
        for (int d = 0; d < 64; d++) o[d] *= corr;
        for (int s = 0; s < nv; s++) {
            const float p = expf(scr[s][tid] - mnew);
            l += p;
            #pragma unroll
            for (int d4 = 0; d4 < 16; d4++) {
                float4 vv = *(const float4*)&vs[s][d4 * 4];   // LDS.128 broadcast
                o[d4*4+0] = fmaf(p, vv.x, o[d4*4+0]);
                o[d4*4+1] = fmaf(p, vv.y, o[d4*4+1]);
                o[d4*4+2] = fmaf(p, vv.z, o[d4*4+2]);
                o[d4*4+3] = fmaf(p, vv.w, o[d4*4+3]);
            }
        }
        m = mnew;
        __syncthreads();
    }

    const float invl = 1.f / l;
    float* orow = g_attn + (size_t)(b * T_ + t) * D_ + h * DH_;
    #pragma unroll
    for (int i = 0; i < 16; i++) {
        *(float4*)(orow + i * 4) = make_float4(o[i*4+0]*invl, o[i*4+1]*invl,
                                               o[i*4+2]*invl, o[i*4+3]*invl);
    }
}

// ---------------- launch -------------------------------------------------------
extern "C" void kernel_launch(void* const* d_in, const int* in_sizes, int n_in,
                              void* d_out, int out_size) {
    const float*        x     = (const float*)d_in[0];
    const unsigned int* mask  = (const unsigned int*)d_in[1];
    const float*        gamma = (const float*)d_in[2];
    const float*        beta  = (const float*)d_in[3];
    const float*        Wqkv  = (const float*)d_in[4];
    const float*        bqkv  = (const float*)d_in[5];
    const float*        Wout  = (const float*)d_in[6];
    const float*        bout  = (const float*)d_in[7];
    float* out = (float*)d_out;

    ln_kernel<<<M_, 256>>>(x, gamma, beta);
    rope_table_kernel<<<(T_ * HALF_D + 255) / 256, 256>>>();
    len_kernel<<<B_, 256>>>(mask);
    gemm_qkv_kernel<<<dim3(N3_ / 128, M_ / 128), 256>>>(Wqkv, bqkv);
    attn_kernel<<<dim3(T_ / 256, B_ * H_), 256>>>();
    gemm_out_kernel<<<dim3(D_ / 128, M_ / 128), 256>>>(Wout, bout, out);
}